// round 7
// baseline (speedup 1.0000x reference)
#include <cuda_runtime.h>
#include <cuda_bf16.h>

#define MARGIN 0.5f
#define EPS 1e-6f
#define WARPS_PER_BLOCK 8
#define THREADS (WARPS_PER_BLOCK * 32)
#define CHUNK 448                      // triplets per block (divisible by 8*4)
#define PER_WARP (CHUNK / WARPS_PER_BLOCK)   // 56 triplets per warp

// Allocation-free scratch; last finishing block resets for graph replays.
__device__ double g_sum = 0.0;
__device__ unsigned int g_count = 0u;

__device__ __forceinline__ float dsq(const float4 a, const float4 b)
{
    float d0 = a.x - b.x + EPS;
    float d1 = a.y - b.y + EPS;
    float d2 = a.z - b.z + EPS;
    float d3 = a.w - b.w + EPS;
    return fmaf(d0, d0, fmaf(d1, d1, fmaf(d2, d2, d3 * d3)));
}

// Contiguous chunk per block; indices staged in SMEM so the gather loads have
// no global-latency dependency at the top of each iteration.
// Half-warp per triplet, dense 256B addressing, 12 gathers in flight per warp.
__global__ void __launch_bounds__(THREADS, 4) triplet_kernel(
    const float* __restrict__ emb,
    const int* __restrict__ a_idx,
    const int* __restrict__ p_idx,
    const int* __restrict__ n_idx,
    int T,
    float* __restrict__ out)
{
    __shared__ int s_a[CHUNK];
    __shared__ int s_p[CHUNK];
    __shared__ int s_n[CHUNK];
    __shared__ float warp_vals[WARPS_PER_BLOCK];

    const int lane = threadIdx.x & 31;
    const int h = lane >> 4;      // which half-warp
    const int s = lane & 15;      // sublane within half
    const int warp_in_block = threadIdx.x >> 5;

    const int start = blockIdx.x * CHUNK;
    const int cnt = min(CHUNK, T - start);   // >= 1 for every launched block

    // Stage this block's indices into SMEM (coalesced, independent loads).
    for (int i = threadIdx.x; i < cnt; i += THREADS) {
        s_a[i] = a_idx[start + i];
        s_p[i] = p_idx[start + i];
        s_n[i] = n_idx[start + i];
    }
    __syncthreads();

    float acc = 0.0f;
    const int wbase = warp_in_block * PER_WARP;

    #pragma unroll 1
    for (int k = 0; k < PER_WARP; k += 4) {
        const int ltA = wbase + k + h;        // local triplets: k, k+1
        const int ltB = wbase + k + 2 + h;    // local triplets: k+2, k+3
        const bool vA = (ltA < cnt);
        const bool vB = (ltB < cnt);
        const int cAi = vA ? ltA : 0;
        const int cBi = vB ? ltB : 0;

        const int iaA = s_a[cAi], ipA = s_p[cAi], inA = s_n[cAi];
        const int iaB = s_a[cBi], ipB = s_p[cBi], inB = s_n[cBi];

        const float4* raA = reinterpret_cast<const float4*>(emb + (size_t)iaA * 128) + s;
        const float4* rpA = reinterpret_cast<const float4*>(emb + (size_t)ipA * 128) + s;
        const float4* rnA = reinterpret_cast<const float4*>(emb + (size_t)inA * 128) + s;
        const float4* raB = reinterpret_cast<const float4*>(emb + (size_t)iaB * 128) + s;
        const float4* rpB = reinterpret_cast<const float4*>(emb + (size_t)ipB * 128) + s;
        const float4* rnB = reinterpret_cast<const float4*>(emb + (size_t)inB * 128) + s;

        // Issue all 12 gathers up front (each covers two dense 256B blocks).
        const float4 aA0 = __ldg(raA),     aA1 = __ldg(raA + 16);
        const float4 pA0 = __ldg(rpA),     pA1 = __ldg(rpA + 16);
        const float4 nA0 = __ldg(rnA),     nA1 = __ldg(rnA + 16);
        const float4 aB0 = __ldg(raB),     aB1 = __ldg(raB + 16);
        const float4 pB0 = __ldg(rpB),     pB1 = __ldg(rpB + 16);
        const float4 nB0 = __ldg(rnB),     nB1 = __ldg(rnB + 16);

        float spA = dsq(aA0, pA0) + dsq(aA1, pA1);
        float snA = dsq(aA0, nA0) + dsq(aA1, nA1);
        float spB = dsq(aB0, pB0) + dsq(aB1, pB1);
        float snB = dsq(aB0, nB0) + dsq(aB1, nB1);

        // Reduce within each 16-lane half (both halves in parallel).
        #pragma unroll
        for (int off = 8; off > 0; off >>= 1) {
            spA += __shfl_down_sync(0xFFFFFFFFu, spA, off, 16);
            snA += __shfl_down_sync(0xFFFFFFFFu, snA, off, 16);
            spB += __shfl_down_sync(0xFFFFFFFFu, spB, off, 16);
            snB += __shfl_down_sync(0xFFFFFFFFu, snB, off, 16);
        }

        if (s == 0) {
            if (vA) acc += fmaxf(sqrtf(spA) - sqrtf(snA) + MARGIN, 0.0f);
            if (vB) acc += fmaxf(sqrtf(spB) - sqrtf(snB) + MARGIN, 0.0f);
        }
    }

    // Full warp reduce of acc (nonzero in lanes 0 and 16).
    #pragma unroll
    for (int off = 16; off > 0; off >>= 1)
        acc += __shfl_down_sync(0xFFFFFFFFu, acc, off);

    if (lane == 0) warp_vals[warp_in_block] = acc;
    __syncthreads();

    if (warp_in_block == 0) {
        float v = (lane < WARPS_PER_BLOCK) ? warp_vals[lane] : 0.0f;
        #pragma unroll
        for (int off = 4; off > 0; off >>= 1)
            v += __shfl_down_sync(0xFFFFFFFFu, v, off);

        if (lane == 0) {
            atomicAdd(&g_sum, (double)v);
            __threadfence();
            unsigned int prev = atomicAdd(&g_count, 1u);
            if (prev == gridDim.x - 1) {
                double total = atomicAdd(&g_sum, 0.0);
                out[0] = (float)(total / (double)T);
                g_sum = 0.0;
                __threadfence();
                atomicExch(&g_count, 0u);
            }
        }
    }
}

extern "C" void kernel_launch(void* const* d_in, const int* in_sizes, int n_in,
                              void* d_out, int out_size) {
    const float* emb   = (const float*)d_in[0];
    // d_in[1] = labels (unused; mining is precomputed in the reference inputs)
    const int* a_idx   = (const int*)d_in[2];
    const int* p_idx   = (const int*)d_in[3];
    const int* n_idx   = (const int*)d_in[4];
    float* out         = (float*)d_out;

    const int T = in_sizes[2];

    int blocks = (T + CHUNK - 1) / CHUNK;   // ~586 for T=262144
    if (blocks < 1) blocks = 1;

    triplet_kernel<<<blocks, THREADS>>>(emb, a_idx, p_idx, n_idx, T, out);
}

// round 8
// speedup vs baseline: 1.0072x; 1.0072x over previous
#include <cuda_runtime.h>
#include <cuda_bf16.h>

#define MARGIN 0.5f
#define EPS 1e-6f
#define WARPS_PER_BLOCK 8
#define THREADS (WARPS_PER_BLOCK * 32)

// Allocation-free scratch; last finishing block resets for graph replays.
__device__ double g_sum = 0.0;
__device__ unsigned int g_count = 0u;

__device__ __forceinline__ float dsq(const float4 a, const float4 b)
{
    float d0 = a.x - b.x + EPS;
    float d1 = a.y - b.y + EPS;
    float d2 = a.z - b.z + EPS;
    float d3 = a.w - b.w + EPS;
    return fmaf(d0, d0, fmaf(d1, d1, fmaf(d2, d2, d3 * d3)));
}

struct GroupIdx {
    int iaA, ipA, inA, iaB, ipB, inB;
    bool vA, vB;
};

struct GBuf {
    float4 aA0, aA1, pA0, pA1, nA0, nA1;
    float4 aB0, aB1, pB0, pB1, nB0, nB1;
};

__device__ __forceinline__ GroupIdx load_idx(const int* __restrict__ a,
                                             const int* __restrict__ p,
                                             const int* __restrict__ n,
                                             int t0, int h, int T)
{
    GroupIdx gi;
    const int tA = t0 + h;
    const int tB = t0 + 2 + h;
    gi.vA = tA < T;
    gi.vB = tB < T;
    const int cA = gi.vA ? tA : 0;
    const int cB = gi.vB ? tB : 0;
    gi.iaA = __ldg(a + cA); gi.ipA = __ldg(p + cA); gi.inA = __ldg(n + cA);
    gi.iaB = __ldg(a + cB); gi.ipB = __ldg(p + cB); gi.inB = __ldg(n + cB);
    return gi;
}

__device__ __forceinline__ void issue_gathers(const float* __restrict__ emb,
                                              const GroupIdx& gi, int s, GBuf& b)
{
    const float4* raA = reinterpret_cast<const float4*>(emb + (size_t)gi.iaA * 128) + s;
    const float4* rpA = reinterpret_cast<const float4*>(emb + (size_t)gi.ipA * 128) + s;
    const float4* rnA = reinterpret_cast<const float4*>(emb + (size_t)gi.inA * 128) + s;
    const float4* raB = reinterpret_cast<const float4*>(emb + (size_t)gi.iaB * 128) + s;
    const float4* rpB = reinterpret_cast<const float4*>(emb + (size_t)gi.ipB * 128) + s;
    const float4* rnB = reinterpret_cast<const float4*>(emb + (size_t)gi.inB * 128) + s;
    b.aA0 = __ldg(raA); b.aA1 = __ldg(raA + 16);
    b.pA0 = __ldg(rpA); b.pA1 = __ldg(rpA + 16);
    b.nA0 = __ldg(rnA); b.nA1 = __ldg(rnA + 16);
    b.aB0 = __ldg(raB); b.aB1 = __ldg(raB + 16);
    b.pB0 = __ldg(rpB); b.pB1 = __ldg(rpB + 16);
    b.nB0 = __ldg(rnB); b.nB1 = __ldg(rnB + 16);
}

__device__ __forceinline__ float consume(const GBuf& b, const GroupIdx& gi, int s)
{
    float spA = dsq(b.aA0, b.pA0) + dsq(b.aA1, b.pA1);
    float snA = dsq(b.aA0, b.nA0) + dsq(b.aA1, b.nA1);
    float spB = dsq(b.aB0, b.pB0) + dsq(b.aB1, b.pB1);
    float snB = dsq(b.aB0, b.nB0) + dsq(b.aB1, b.nB1);

    #pragma unroll
    for (int off = 8; off > 0; off >>= 1) {
        spA += __shfl_down_sync(0xFFFFFFFFu, spA, off, 16);
        snA += __shfl_down_sync(0xFFFFFFFFu, snA, off, 16);
        spB += __shfl_down_sync(0xFFFFFFFFu, spB, off, 16);
        snB += __shfl_down_sync(0xFFFFFFFFu, snB, off, 16);
    }

    float r = 0.0f;
    if (s == 0) {
        if (gi.vA) r += fmaxf(sqrtf(spA) - sqrtf(snA) + MARGIN, 0.0f);
        if (gi.vB) r += fmaxf(sqrtf(spB) - sqrtf(snB) + MARGIN, 0.0f);
    }
    return r;
}

// Grid-stride over groups of 4 triplets, depth-2 software pipeline:
// group k+1's index loads + gathers are issued before group k is consumed,
// so gather loads stay in flight ~continuously.
__global__ void __launch_bounds__(THREADS, 2) triplet_kernel(
    const float* __restrict__ emb,
    const int* __restrict__ a_idx,
    const int* __restrict__ p_idx,
    const int* __restrict__ n_idx,
    int T,
    float* __restrict__ out)
{
    const int lane = threadIdx.x & 31;
    const int h = lane >> 4;      // half-warp id
    const int s = lane & 15;      // sublane within half
    const int warp_in_block = threadIdx.x >> 5;
    const int gwarp = blockIdx.x * WARPS_PER_BLOCK + warp_in_block;
    const int nwarps = gridDim.x * WARPS_PER_BLOCK;
    const int stride = nwarps * 4;

    float acc = 0.0f;

    int t = gwarp * 4;
    if (t < T) {
        GroupIdx gi0, gi1;
        GBuf b0, b1;

        gi0 = load_idx(a_idx, p_idx, n_idx, t, h, T);
        issue_gathers(emb, gi0, s, b0);
        int t1 = t + stride;

        while (true) {
            if (t1 < T) {
                gi1 = load_idx(a_idx, p_idx, n_idx, t1, h, T);
                issue_gathers(emb, gi1, s, b1);
            }
            acc += consume(b0, gi0, s);
            t = t1 + stride;
            if (t1 >= T) break;

            if (t < T) {
                gi0 = load_idx(a_idx, p_idx, n_idx, t, h, T);
                issue_gathers(emb, gi0, s, b0);
            }
            acc += consume(b1, gi1, s);
            t1 = t + stride;
            if (t >= T) break;
        }
    }

    // Full warp reduce of acc (nonzero in lanes 0 and 16).
    #pragma unroll
    for (int off = 16; off > 0; off >>= 1)
        acc += __shfl_down_sync(0xFFFFFFFFu, acc, off);

    __shared__ float warp_vals[WARPS_PER_BLOCK];
    if (lane == 0) warp_vals[warp_in_block] = acc;
    __syncthreads();

    if (warp_in_block == 0) {
        float v = (lane < WARPS_PER_BLOCK) ? warp_vals[lane] : 0.0f;
        #pragma unroll
        for (int off = 4; off > 0; off >>= 1)
            v += __shfl_down_sync(0xFFFFFFFFu, v, off);

        if (lane == 0) {
            atomicAdd(&g_sum, (double)v);
            __threadfence();
            unsigned int prev = atomicAdd(&g_count, 1u);
            if (prev == gridDim.x - 1) {
                double total = atomicAdd(&g_sum, 0.0);
                out[0] = (float)(total / (double)T);
                g_sum = 0.0;
                __threadfence();
                atomicExch(&g_count, 0u);
            }
        }
    }
}

extern "C" void kernel_launch(void* const* d_in, const int* in_sizes, int n_in,
                              void* d_out, int out_size) {
    const float* emb   = (const float*)d_in[0];
    // d_in[1] = labels (unused; mining is precomputed in the reference inputs)
    const int* a_idx   = (const int*)d_in[2];
    const int* p_idx   = (const int*)d_in[3];
    const int* n_idx   = (const int*)d_in[4];
    float* out         = (float*)d_out;

    const int T = in_sizes[2];

    // Persistent grid: 2 resident blocks per SM on 148 SMs.
    int blocks = 148 * 2;
    int max_blocks = (T + WARPS_PER_BLOCK * 4 - 1) / (WARPS_PER_BLOCK * 4);
    if (blocks > max_blocks) blocks = max_blocks;
    if (blocks < 1) blocks = 1;

    triplet_kernel<<<blocks, THREADS>>>(emb, a_idx, p_idx, n_idx, T, out);
}

// round 9
// speedup vs baseline: 1.1883x; 1.1798x over previous
#include <cuda_runtime.h>
#include <cuda_bf16.h>

#define MARGIN 0.5f
#define EPS 1e-6f
#define WARPS_PER_BLOCK 8
#define THREADS (WARPS_PER_BLOCK * 32)

// Allocation-free scratch; last finishing block resets for graph replays.
__device__ double g_sum = 0.0;
__device__ unsigned int g_count = 0u;

__device__ __forceinline__ float dsq(const float4 a, const float4 b)
{
    float d0 = a.x - b.x + EPS;
    float d1 = a.y - b.y + EPS;
    float d2 = a.z - b.z + EPS;
    float d3 = a.w - b.w + EPS;
    return fmaf(d0, d0, fmaf(d1, d1, fmaf(d2, d2, d3 * d3)));
}

// Half-warp per triplet, dense 256B addressing, 12 gathers in flight per warp,
// next-iteration index loads prefetched behind the current gathers.
__global__ void __launch_bounds__(THREADS, 4) triplet_kernel(
    const float* __restrict__ emb,
    const int* __restrict__ a_idx,
    const int* __restrict__ p_idx,
    const int* __restrict__ n_idx,
    int T,
    float* __restrict__ out)
{
    const int lane = threadIdx.x & 31;
    const int h = lane >> 4;      // half-warp id
    const int s = lane & 15;      // sublane within half
    const int warp_in_block = threadIdx.x >> 5;
    const int gwarp = blockIdx.x * WARPS_PER_BLOCK + warp_in_block;
    const int nwarps = gridDim.x * WARPS_PER_BLOCK;
    const int stride = nwarps * 4;

    float acc = 0.0f;

    int t0 = gwarp * 4;
    if (t0 < T) {
        // Load first group's indices.
        int tA = t0 + h;
        int tB = t0 + 2 + h;
        bool vA = tA < T, vB = tB < T;
        int iaA = __ldg(a_idx + (vA ? tA : 0));
        int ipA = __ldg(p_idx + (vA ? tA : 0));
        int inA = __ldg(n_idx + (vA ? tA : 0));
        int iaB = __ldg(a_idx + (vB ? tB : 0));
        int ipB = __ldg(p_idx + (vB ? tB : 0));
        int inB = __ldg(n_idx + (vB ? tB : 0));

        for (; t0 < T; t0 += stride) {
            // Issue all 12 gathers for the current group.
            const float4* raA = reinterpret_cast<const float4*>(emb + (size_t)iaA * 128) + s;
            const float4* rpA = reinterpret_cast<const float4*>(emb + (size_t)ipA * 128) + s;
            const float4* rnA = reinterpret_cast<const float4*>(emb + (size_t)inA * 128) + s;
            const float4* raB = reinterpret_cast<const float4*>(emb + (size_t)iaB * 128) + s;
            const float4* rpB = reinterpret_cast<const float4*>(emb + (size_t)ipB * 128) + s;
            const float4* rnB = reinterpret_cast<const float4*>(emb + (size_t)inB * 128) + s;

            const float4 aA0 = __ldg(raA), aA1 = __ldg(raA + 16);
            const float4 pA0 = __ldg(rpA), pA1 = __ldg(rpA + 16);
            const float4 nA0 = __ldg(rnA), nA1 = __ldg(rnA + 16);
            const float4 aB0 = __ldg(raB), aB1 = __ldg(raB + 16);
            const float4 pB0 = __ldg(rpB), pB1 = __ldg(rpB + 16);
            const float4 nB0 = __ldg(rnB), nB1 = __ldg(rnB + 16);

            const bool cvA = vA, cvB = vB;

            // Prefetch next group's indices while the gathers are in flight.
            const int tn = t0 + stride;
            if (tn < T) {
                tA = tn + h;
                tB = tn + 2 + h;
                vA = tA < T; vB = tB < T;
                iaA = __ldg(a_idx + (vA ? tA : 0));
                ipA = __ldg(p_idx + (vA ? tA : 0));
                inA = __ldg(n_idx + (vA ? tA : 0));
                iaB = __ldg(a_idx + (vB ? tB : 0));
                ipB = __ldg(p_idx + (vB ? tB : 0));
                inB = __ldg(n_idx + (vB ? tB : 0));
            }

            float spA = dsq(aA0, pA0) + dsq(aA1, pA1);
            float snA = dsq(aA0, nA0) + dsq(aA1, nA1);
            float spB = dsq(aB0, pB0) + dsq(aB1, pB1);
            float snB = dsq(aB0, nB0) + dsq(aB1, nB1);

            // Reduce within each 16-lane half (both halves in parallel).
            #pragma unroll
            for (int off = 8; off > 0; off >>= 1) {
                spA += __shfl_down_sync(0xFFFFFFFFu, spA, off, 16);
                snA += __shfl_down_sync(0xFFFFFFFFu, snA, off, 16);
                spB += __shfl_down_sync(0xFFFFFFFFu, spB, off, 16);
                snB += __shfl_down_sync(0xFFFFFFFFu, snB, off, 16);
            }

            if (s == 0) {
                if (cvA) acc += fmaxf(sqrtf(spA) - sqrtf(snA) + MARGIN, 0.0f);
                if (cvB) acc += fmaxf(sqrtf(spB) - sqrtf(snB) + MARGIN, 0.0f);
            }
        }
    }

    // Full warp reduce of acc (nonzero in lanes 0 and 16).
    #pragma unroll
    for (int off = 16; off > 0; off >>= 1)
        acc += __shfl_down_sync(0xFFFFFFFFu, acc, off);

    __shared__ float warp_vals[WARPS_PER_BLOCK];
    if (lane == 0) warp_vals[warp_in_block] = acc;
    __syncthreads();

    if (warp_in_block == 0) {
        float v = (lane < WARPS_PER_BLOCK) ? warp_vals[lane] : 0.0f;
        #pragma unroll
        for (int off = 4; off > 0; off >>= 1)
            v += __shfl_down_sync(0xFFFFFFFFu, v, off);

        if (lane == 0) {
            atomicAdd(&g_sum, (double)v);
            __threadfence();
            unsigned int prev = atomicAdd(&g_count, 1u);
            if (prev == gridDim.x - 1) {
                double total = atomicAdd(&g_sum, 0.0);
                out[0] = (float)(total / (double)T);
                g_sum = 0.0;
                __threadfence();
                atomicExch(&g_count, 0u);
            }
        }
    }
}

extern "C" void kernel_launch(void* const* d_in, const int* in_sizes, int n_in,
                              void* d_out, int out_size) {
    const float* emb   = (const float*)d_in[0];
    // d_in[1] = labels (unused; mining is precomputed in the reference inputs)
    const int* a_idx   = (const int*)d_in[2];
    const int* p_idx   = (const int*)d_in[3];
    const int* n_idx   = (const int*)d_in[4];
    float* out         = (float*)d_out;

    const int T = in_sizes[2];

    // Persistent grid: 4 resident blocks per SM on 148 SMs.
    int blocks = 148 * 4;
    int max_blocks = (T + WARPS_PER_BLOCK * 4 - 1) / (WARPS_PER_BLOCK * 4);
    if (blocks > max_blocks) blocks = max_blocks;
    if (blocks < 1) blocks = 1;

    triplet_kernel<<<blocks, THREADS>>>(emb, a_idx, p_idx, n_idx, T, out);
}